// round 11
// baseline (speedup 1.0000x reference)
#include <cuda_runtime.h>
#include <cuda_fp16.h>
#include <cuda_bf16.h>
#include <cstdint>

#define N_NODES 100000
#define C_DIM   256
#define CSR_CAP 3400000
#define SCAN_B  1024

// GEMM tiling (fp16 HMMA m16n8k16; smem holds k-PAIRS packed in 32-bit words)
#define BM 128
#define BN 128
#define BK 32
#define KP (BK / 2)      // 16 k-pair rows per slab
#define AS_STRIDE 129    // words per kp-row of As (odd -> conflict-free)
#define BS_STRIDE 132    // words per kp-row of Bs

#define AUX_BLOCKS 512
#define HALF_TILES 391       // row tiles per GEMM half (391*128 = 50048)
#define HALF_ROWS  50048
#define AGG1_AUX_NODES (N_NODES - HALF_ROWS)              // 49952
#define AGG1_AUX_BLOCKS ((AGG1_AUX_NODES + 7) / 8)        // 6244

// ---------------- device scratch (no allocations allowed) ----------------
__device__ int    g_deg[N_NODES];
__device__ int    g_offs[N_NODES + 1];
__device__ int    g_cursor[N_NODES];
__device__ float  g_dis[N_NODES];
__device__ int    g_blockSums[SCAN_B];
__device__ int    g_csr_src[CSR_CAP];
__device__ __half g_bufT[(size_t)N_NODES * C_DIM];  // transformed features (fp16)
__device__ __half g_bufH[(size_t)N_NODES * C_DIM];  // layer-1 output (fp16)

// ---------------- degree init ----------------
__global__ void k_deg_init() {
    int i = blockIdx.x * blockDim.x + threadIdx.x;
    if (i < N_NODES) g_deg[i] = 1;   // self-loop
}

// ---------------- exclusive scan of degrees -> CSR row offsets ----------------
__global__ void k_scan1() {
    __shared__ int s[SCAN_B];
    int tid = threadIdx.x;
    int i = blockIdx.x * SCAN_B + tid;
    int v = (i < N_NODES) ? g_deg[i] : 0;
    s[tid] = v;
    __syncthreads();
#pragma unroll
    for (int off = 1; off < SCAN_B; off <<= 1) {
        int a = (tid >= off) ? s[tid - off] : 0;
        __syncthreads();
        s[tid] += a;
        __syncthreads();
    }
    if (i < N_NODES) g_offs[i] = s[tid] - v;
    if (tid == SCAN_B - 1) g_blockSums[blockIdx.x] = s[tid];
}

__global__ void k_scan2(int nblk) {
    __shared__ int s[SCAN_B];
    int tid = threadIdx.x;
    int v = (tid < nblk) ? g_blockSums[tid] : 0;
    s[tid] = v;
    __syncthreads();
#pragma unroll
    for (int off = 1; off < SCAN_B; off <<= 1) {
        int a = (tid >= off) ? s[tid - off] : 0;
        __syncthreads();
        s[tid] += a;
        __syncthreads();
    }
    if (tid < nblk) g_blockSums[tid] = s[tid] - v;
}

// scan finalize + deg_inv_sqrt + deterministic self-loop in each row's LAST slot
__global__ void k_scan3() {
    int i = blockIdx.x * blockDim.x + threadIdx.x;
    if (i < N_NODES) {
        int deg = g_deg[i];
        int e = g_offs[i] + g_blockSums[i >> 10];
        g_offs[i] = e;
        g_cursor[i] = e;
        g_dis[i] = rsqrtf((float)deg);
        g_csr_src[e + deg - 1] = i;            // self-loop; weight dis^2 falls out
        if (i == N_NODES - 1) g_offs[N_NODES] = e + deg;
    }
}

// ---------------- fp16 HMMA helpers ----------------
__device__ __forceinline__ void mma_f16(float c[4], const uint32_t a[4],
                                        const uint32_t b[2]) {
    asm volatile(
        "mma.sync.aligned.m16n8k16.row.col.f32.f16.f16.f32 "
        "{%0,%1,%2,%3}, {%4,%5,%6,%7}, {%8,%9}, {%0,%1,%2,%3};"
        : "+f"(c[0]), "+f"(c[1]), "+f"(c[2]), "+f"(c[3])
        : "r"(a[0]), "r"(a[1]), "r"(a[2]), "r"(a[3]), "r"(b[0]), "r"(b[1]));
}

__device__ __forceinline__ uint2 ldPack4(const float* p) {
    float4 v = *(const float4*)p;
    uint2 w;
    __half2 h0 = __floats2half2_rn(v.x, v.y);
    __half2 h1 = __floats2half2_rn(v.z, v.w);
    w.x = *(uint32_t*)&h0;
    w.y = *(uint32_t*)&h1;
    return w;
}
__device__ __forceinline__ uint2 ldPack4(const __half* p) {
    return *(const uint2*)p;     // already fp16, k-contiguous
}

// ---------------- fp16 gather helper: accumulate one row into acc[8] ----------
__device__ __forceinline__ void acc_row(float acc[8], const __half* __restrict__ buf,
                                        int s, float wt, int lane) {
    uint4 v = ((const uint4*)(buf + (size_t)s * 256))[lane];
    const __half2* hp = (const __half2*)&v;
#pragma unroll
    for (int j = 0; j < 4; j++) {
        float2 f = __half22float2(hp[j]);
        acc[2 * j + 0] += wt * f.x;
        acc[2 * j + 1] += wt * f.y;
    }
}

// warp-cooperative edge loop: 32 edge indices fetched coalesced by the warp,
// broadcast via shfl; the 32 row-gathers per chunk are fully independent (MLP~32)
__device__ __forceinline__ void agg_edges(float acc[8], const __half* __restrict__ buf,
                                          int beg, int end, float disw, int lane) {
    for (int e0 = beg; e0 < end; e0 += 32) {
        int n = end - e0;
        if (n > 32) n = 32;
        int ee = e0 + lane;
        if (ee >= end) ee = end - 1;           // deg >= 1 always
        int myIdx = g_csr_src[ee];
        float myW = g_dis[myIdx] * disw;
        for (int j = 0; j < n; j++) {
            int s = __shfl_sync(0xFFFFFFFFu, myIdx, j);
            float wt = __shfl_sync(0xFFFFFFFFu, myW, j);
            acc_row(acc, buf, s, wt, lane);
        }
    }
}

// shared agg-relu body (writes fp16 row into g_bufH)
__device__ __forceinline__ void agg_relu_node(int w, const float* __restrict__ bias,
                                              int lane) {
    int beg = g_offs[w], end = g_offs[w + 1];
    float disw = g_dis[w];
    float acc[8];
#pragma unroll
    for (int j = 0; j < 8; j++) acc[j] = 0.f;
    agg_edges(acc, g_bufT, beg, end, disw, lane);

    float4 b0 = ((const float4*)bias)[lane * 2];
    float4 b1 = ((const float4*)bias)[lane * 2 + 1];
    __half2 h[4];
    h[0] = __floats2half2_rn(fmaxf(acc[0] + b0.x, 0.f), fmaxf(acc[1] + b0.y, 0.f));
    h[1] = __floats2half2_rn(fmaxf(acc[2] + b0.z, 0.f), fmaxf(acc[3] + b0.w, 0.f));
    h[2] = __floats2half2_rn(fmaxf(acc[4] + b1.x, 0.f), fmaxf(acc[5] + b1.y, 0.f));
    h[3] = __floats2half2_rn(fmaxf(acc[6] + b1.z, 0.f), fmaxf(acc[7] + b1.w, 0.f));
    ((uint4*)(g_bufH + (size_t)w * 256))[lane] = *(uint4*)h;
}

// ---------------- fp16 tensor-core GEMM (+ optional fused aux CTAs) ----------
// AUX: 0 = none, 1 = degree histogram, 2 = CSR fill, 3 = agg1 (layer-1 agg+relu).
// Aux CTAs occupy block indices [0, auxBlocks).
template <typename TA, int AUX>
__global__ __launch_bounds__(256, 2) void k_gemm_aux(const TA* __restrict__ A,
                                                     const float* __restrict__ Bw,
                                                     int M, int rowTileOff,
                                                     int nRowTiles,
                                                     const int* __restrict__ ei,
                                                     int E, int auxBlocks,
                                                     const float* __restrict__ bias,
                                                     int nodeOff) {
    if (AUX != 0 && (int)blockIdx.x < auxBlocks) {
        if (AUX == 1) {
            int t = blockIdx.x * 256 + threadIdx.x;
            int stride = auxBlocks * 256;
            for (int e = t; e < E; e += stride)
                atomicAdd(&g_deg[ei[E + e]], 1);
        } else if (AUX == 2) {
            int t = blockIdx.x * 256 + threadIdx.x;
            int stride = auxBlocks * 256;
            for (int e = t; e < E; e += stride) {
                int s = ei[e];
                int d = ei[E + e];
                int pos = atomicAdd(&g_cursor[d], 1);
                g_csr_src[pos] = s;
            }
        } else {  // AUX == 3: layer-1 aggregation for nodes [nodeOff, ...)
            int w = nodeOff + (blockIdx.x * 256 + threadIdx.x) / 32;
            int lane = threadIdx.x & 31;
            if (w < N_NODES) agg_relu_node(w, bias, lane);
        }
        return;
    }

    const TA* Ap = A ? A : (const TA*)g_bufH;   // layer 2 reads g_bufH (fp16)
    __shared__ uint32_t As[KP * AS_STRIDE];     // [kp][m] packed half2
    __shared__ uint32_t Bs[KP * BS_STRIDE];     // [kp][n] packed half2

    int tile = blockIdx.x - auxBlocks;
    int rowBase = (rowTileOff + tile % nRowTiles) * BM;
    int colBase = (tile / nRowTiles) * BN;

    int tid = threadIdx.x;
    int lane = tid & 31;
    int warp = tid >> 5;
    int warpM = warp & 3;
    int warpN = warp >> 2;
    int g = lane >> 2;
    int t = lane & 3;

    float c[2][8][4];
#pragma unroll
    for (int mt = 0; mt < 2; mt++)
#pragma unroll
        for (int nt = 0; nt < 8; nt++)
#pragma unroll
            for (int j = 0; j < 4; j++) c[mt][nt][j] = 0.f;

    for (int k0 = 0; k0 < 256; k0 += BK) {
#pragma unroll
        for (int it = 0; it < 4; it++) {
            int id = tid + it * 256;
            int k4 = id & 7;
            int m = id >> 3;
            int grow = rowBase + m;
            uint2 w = make_uint2(0u, 0u);
            if (grow < M)
                w = ldPack4(Ap + (size_t)grow * 256 + k0 + k4 * 4);
            As[(k4 * 2 + 0) * AS_STRIDE + m] = w.x;
            As[(k4 * 2 + 1) * AS_STRIDE + m] = w.y;
        }
#pragma unroll
        for (int it = 0; it < 2; it++) {
            int id = tid + it * 256;
            int n4 = id & 31;
            int kp = id >> 5;
            const float* r0 = Bw + (size_t)(k0 + kp * 2 + 0) * 256 + colBase + n4 * 4;
            const float* r1 = Bw + (size_t)(k0 + kp * 2 + 1) * 256 + colBase + n4 * 4;
            float4 va = *(const float4*)r0;
            float4 vb = *(const float4*)r1;
            uint4 w;
            __half2 h;
            h = __floats2half2_rn(va.x, vb.x); w.x = *(uint32_t*)&h;
            h = __floats2half2_rn(va.y, vb.y); w.y = *(uint32_t*)&h;
            h = __floats2half2_rn(va.z, vb.z); w.z = *(uint32_t*)&h;
            h = __floats2half2_rn(va.w, vb.w); w.w = *(uint32_t*)&h;
            *(uint4*)&Bs[kp * BS_STRIDE + n4 * 4] = w;
        }
        __syncthreads();

#pragma unroll
        for (int s = 0; s < 2; s++) {
            int kp0 = s * 8;
            uint32_t a[2][4], b[8][2];
#pragma unroll
            for (int mt = 0; mt < 2; mt++) {
                int m = warpM * 32 + mt * 16 + g;
                a[mt][0] = As[(kp0 + t) * AS_STRIDE + m];
                a[mt][1] = As[(kp0 + t) * AS_STRIDE + m + 8];
                a[mt][2] = As[(kp0 + t + 4) * AS_STRIDE + m];
                a[mt][3] = As[(kp0 + t + 4) * AS_STRIDE + m + 8];
            }
#pragma unroll
            for (int nt = 0; nt < 8; nt++) {
                int n = warpN * 64 + nt * 8 + g;
                b[nt][0] = Bs[(kp0 + t) * BS_STRIDE + n];
                b[nt][1] = Bs[(kp0 + t + 4) * BS_STRIDE + n];
            }
#pragma unroll
            for (int mt = 0; mt < 2; mt++)
#pragma unroll
                for (int nt = 0; nt < 8; nt++) mma_f16(c[mt][nt], a[mt], b[nt]);
        }
        __syncthreads();
    }

#pragma unroll
    for (int mt = 0; mt < 2; mt++) {
        int grow = rowBase + warpM * 32 + mt * 16 + g;
#pragma unroll
        for (int nt = 0; nt < 8; nt++) {
            int gcol = colBase + warpN * 64 + nt * 8 + t * 2;
            if (grow < M)
                *(__half2*)(g_bufT + (size_t)grow * 256 + gcol) =
                    __floats2half2_rn(c[mt][nt][0], c[mt][nt][1]);
            if (grow + 8 < M)
                *(__half2*)(g_bufT + (size_t)(grow + 8) * 256 + gcol) =
                    __floats2half2_rn(c[mt][nt][2], c[mt][nt][3]);
        }
    }
}

// ---------------- standalone layer-1 aggregation (node range) -----------------
__global__ __launch_bounds__(256) void k_agg_relu(const float* __restrict__ bias,
                                                  int nodeOff, int nNodes) {
    int w = nodeOff + (blockIdx.x * blockDim.x + threadIdx.x) / 32;
    int lane = threadIdx.x & 31;
    if (w >= nodeOff + nNodes) return;
    agg_relu_node(w, bias, lane);
}

// ---------------- agg layer 2 fused with final linear ------------------------
__global__ __launch_bounds__(256) void k_agg_final(const float* __restrict__ b2,
                                                   const float* __restrict__ Wl,
                                                   const float* __restrict__ bl,
                                                   float* __restrict__ out) {
    int w = (blockIdx.x * blockDim.x + threadIdx.x) >> 5;
    int lane = threadIdx.x & 31;
    if (w >= N_NODES) return;
    int beg = g_offs[w], end = g_offs[w + 1];
    float disw = g_dis[w];
    float acc[8];
#pragma unroll
    for (int j = 0; j < 8; j++) acc[j] = 0.f;
    agg_edges(acc, g_bufT, beg, end, disw, lane);

    float4 b0 = ((const float4*)b2)[lane * 2];
    float4 b1 = ((const float4*)b2)[lane * 2 + 1];
    float4 w0 = ((const float4*)Wl)[lane * 2];
    float4 w1 = ((const float4*)Wl)[lane * 2 + 1];
    float s =
        fmaxf(acc[0] + b0.x, 0.f) * w0.x + fmaxf(acc[1] + b0.y, 0.f) * w0.y +
        fmaxf(acc[2] + b0.z, 0.f) * w0.z + fmaxf(acc[3] + b0.w, 0.f) * w0.w +
        fmaxf(acc[4] + b1.x, 0.f) * w1.x + fmaxf(acc[5] + b1.y, 0.f) * w1.y +
        fmaxf(acc[6] + b1.z, 0.f) * w1.z + fmaxf(acc[7] + b1.w, 0.f) * w1.w;
#pragma unroll
    for (int o = 16; o > 0; o >>= 1) s += __shfl_xor_sync(0xFFFFFFFFu, s, o);
    if (lane == 0) out[w] = s + bl[0];
}

// ---------------- launch ----------------
extern "C" void kernel_launch(void* const* d_in, const int* in_sizes, int n_in,
                              void* d_out, int out_size) {
    const float* x  = (const float*)d_in[0];
    const int*   ei = (const int*)d_in[1];     // edge_index is int32 (JAX x64 disabled)
    const float* W1 = (const float*)d_in[2];
    const float* b1 = (const float*)d_in[3];
    const float* W2 = (const float*)d_in[4];
    const float* b2 = (const float*)d_in[5];
    const float* Wl = (const float*)d_in[6];
    const float* bl = (const float*)d_in[7];
    float* out = (float*)d_out;

    int E = in_sizes[1] / 2;
    int nblk = (N_NODES + SCAN_B - 1) / SCAN_B;           // 98
    int node_blocks = (N_NODES + 255) / 256;              // 391
    int agg_blocks = (N_NODES * 32 + 255) / 256;          // 12500 (warp per node)
    int agg1_h1_blocks = (HALF_ROWS + 7) / 8;             // 6256

    k_deg_init<<<node_blocks, 256>>>();

    // GEMM1 first half (rows [0, 50048)) overlapped with degree histogram
    k_gemm_aux<float, 1><<<AUX_BLOCKS + HALF_TILES * 2, 256>>>(
        x, W1, N_NODES, 0, HALF_TILES, ei, E, AUX_BLOCKS, nullptr, 0);

    // serial neck: offsets + dis + self-loops
    k_scan1<<<nblk, SCAN_B>>>();
    k_scan2<<<1, SCAN_B>>>(nblk);
    k_scan3<<<node_blocks, 256>>>();

    // GEMM1 second half (rows [50048, 100000)) overlapped with CSR fill
    k_gemm_aux<float, 2><<<AUX_BLOCKS + HALF_TILES * 2, 256>>>(
        x, W1, N_NODES, HALF_TILES, HALF_TILES, ei, E, AUX_BLOCKS, nullptr, 0);

    // layer-1 aggregation, first half of nodes
    k_agg_relu<<<agg1_h1_blocks, 256>>>(b1, 0, HALF_ROWS);

    // GEMM2 on rows [0, 50048) overlapped with agg1 on nodes [50048, 100000)
    k_gemm_aux<__half, 3><<<AGG1_AUX_BLOCKS + HALF_TILES * 2, 256>>>(
        (const __half*)nullptr, W2, N_NODES, 0, HALF_TILES, nullptr, 0,
        AGG1_AUX_BLOCKS, b1, HALF_ROWS);

    // GEMM2 on rows [50048, 100000)
    k_gemm_aux<__half, 0><<<HALF_TILES * 2, 256>>>(
        (const __half*)nullptr, W2, N_NODES, HALF_TILES, HALF_TILES, nullptr, 0,
        0, nullptr, 0);

    // layer-2 aggregation + final linear head
    k_agg_final<<<agg_blocks, 256>>>(b2, Wl, bl, out);
}

// round 12
// speedup vs baseline: 1.2126x; 1.2126x over previous
#include <cuda_runtime.h>
#include <cuda_fp16.h>
#include <cuda_bf16.h>
#include <cstdint>

#define N_NODES 100000
#define C_DIM   256
#define CSR_CAP 3400000
#define SCAN_B  1024

// GEMM tiling (fp16 HMMA m16n8k16; smem holds k-PAIRS packed in 32-bit words)
#define BM 128
#define BN 128
#define BK 32
#define KP (BK / 2)      // 16 k-pair rows per slab
#define AS_STRIDE 129    // words per kp-row of As (odd -> conflict-free)
#define BS_STRIDE 132    // words per kp-row of Bs

#define AUX_BLOCKS 512
#define HALF_TILES 391   // row tiles per GEMM1 half (391*128 = 50048)
#define FULL_TILES 782

// ---------------- device scratch (no allocations allowed) ----------------
__device__ int    g_deg[N_NODES];
__device__ int    g_offs[N_NODES + 1];
__device__ int    g_cursor[N_NODES];
__device__ float  g_dis[N_NODES];
__device__ int    g_blockSums[SCAN_B];
__device__ int    g_csr_src[CSR_CAP];
__device__ __half g_bufT[(size_t)N_NODES * C_DIM];  // transformed features (fp16)
__device__ __half g_bufH[(size_t)N_NODES * C_DIM];  // layer-1 output (fp16)

// ---------------- degree init ----------------
__global__ void k_deg_init() {
    int i = blockIdx.x * blockDim.x + threadIdx.x;
    if (i < N_NODES) g_deg[i] = 1;   // self-loop
}

// ---------------- exclusive scan of degrees -> CSR row offsets ----------------
__global__ void k_scan1() {
    __shared__ int s[SCAN_B];
    int tid = threadIdx.x;
    int i = blockIdx.x * SCAN_B + tid;
    int v = (i < N_NODES) ? g_deg[i] : 0;
    s[tid] = v;
    __syncthreads();
#pragma unroll
    for (int off = 1; off < SCAN_B; off <<= 1) {
        int a = (tid >= off) ? s[tid - off] : 0;
        __syncthreads();
        s[tid] += a;
        __syncthreads();
    }
    if (i < N_NODES) g_offs[i] = s[tid] - v;
    if (tid == SCAN_B - 1) g_blockSums[blockIdx.x] = s[tid];
}

__global__ void k_scan2(int nblk) {
    __shared__ int s[SCAN_B];
    int tid = threadIdx.x;
    int v = (tid < nblk) ? g_blockSums[tid] : 0;
    s[tid] = v;
    __syncthreads();
#pragma unroll
    for (int off = 1; off < SCAN_B; off <<= 1) {
        int a = (tid >= off) ? s[tid - off] : 0;
        __syncthreads();
        s[tid] += a;
        __syncthreads();
    }
    if (tid < nblk) g_blockSums[tid] = s[tid] - v;
}

// scan finalize + deg_inv_sqrt + deterministic self-loop in each row's LAST slot
__global__ void k_scan3() {
    int i = blockIdx.x * blockDim.x + threadIdx.x;
    if (i < N_NODES) {
        int deg = g_deg[i];
        int e = g_offs[i] + g_blockSums[i >> 10];
        g_offs[i] = e;
        g_cursor[i] = e;
        g_dis[i] = rsqrtf((float)deg);
        g_csr_src[e + deg - 1] = i;            // self-loop; weight dis^2 falls out
        if (i == N_NODES - 1) g_offs[N_NODES] = e + deg;
    }
}

// ---------------- fp16 HMMA helpers ----------------
__device__ __forceinline__ void mma_f16(float c[4], const uint32_t a[4],
                                        const uint32_t b[2]) {
    asm volatile(
        "mma.sync.aligned.m16n8k16.row.col.f32.f16.f16.f32 "
        "{%0,%1,%2,%3}, {%4,%5,%6,%7}, {%8,%9}, {%0,%1,%2,%3};"
        : "+f"(c[0]), "+f"(c[1]), "+f"(c[2]), "+f"(c[3])
        : "r"(a[0]), "r"(a[1]), "r"(a[2]), "r"(a[3]), "r"(b[0]), "r"(b[1]));
}

__device__ __forceinline__ uint2 ldPack4(const float* p) {
    float4 v = *(const float4*)p;
    uint2 w;
    __half2 h0 = __floats2half2_rn(v.x, v.y);
    __half2 h1 = __floats2half2_rn(v.z, v.w);
    w.x = *(uint32_t*)&h0;
    w.y = *(uint32_t*)&h1;
    return w;
}
__device__ __forceinline__ uint2 ldPack4(const __half* p) {
    return *(const uint2*)p;     // already fp16, k-contiguous
}

// ---------------- fp16 tensor-core GEMM (+ optional fused aux CTAs) ----------
// AUX: 0 = none, 1 = degree histogram, 2 = CSR fill (aux CTAs at low block idx)
template <typename TA, int AUX>
__global__ __launch_bounds__(256, 2) void k_gemm_aux(const TA* __restrict__ A,
                                                     const float* __restrict__ Bw,
                                                     int M, int rowTileOff,
                                                     int nRowTiles,
                                                     const int* __restrict__ ei,
                                                     int E, int auxBlocks) {
    if (AUX != 0 && (int)blockIdx.x < auxBlocks) {
        int t = blockIdx.x * 256 + threadIdx.x;
        int stride = auxBlocks * 256;
        if (AUX == 1) {
            for (int e = t; e < E; e += stride)
                atomicAdd(&g_deg[ei[E + e]], 1);
        } else {
            for (int e = t; e < E; e += stride) {
                int s = ei[e];
                int d = ei[E + e];
                int pos = atomicAdd(&g_cursor[d], 1);
                g_csr_src[pos] = s;
            }
        }
        return;
    }

    const TA* Ap = A ? A : (const TA*)g_bufH;   // layer 2 reads g_bufH (fp16)
    __shared__ uint32_t As[KP * AS_STRIDE];     // [kp][m] packed half2 (k-pairs)
    __shared__ uint32_t Bs[KP * BS_STRIDE];     // [kp][n] packed half2 (k-pairs)

    int tile = blockIdx.x - auxBlocks;
    int rowBase = (rowTileOff + tile % nRowTiles) * BM;
    int colBase = (tile / nRowTiles) * BN;

    int tid = threadIdx.x;
    int lane = tid & 31;
    int warp = tid >> 5;
    int warpM = warp & 3;          // 32 rows each
    int warpN = warp >> 2;         // 64 cols each
    int g = lane >> 2;             // 0..7 group
    int t = lane & 3;              // 0..3 thread-in-group

    float c[2][8][4];
#pragma unroll
    for (int mt = 0; mt < 2; mt++)
#pragma unroll
        for (int nt = 0; nt < 8; nt++)
#pragma unroll
            for (int j = 0; j < 4; j++) c[mt][nt][j] = 0.f;

    for (int k0 = 0; k0 < 256; k0 += BK) {
        // A tile: 128 rows x 32 k -> [kp][m] packed. id -> (m, k4): k4 = id&7
#pragma unroll
        for (int it = 0; it < 4; it++) {
            int id = tid + it * 256;
            int k4 = id & 7;           // which 4-k chunk
            int m = id >> 3;
            int grow = rowBase + m;
            uint2 w = make_uint2(0u, 0u);
            if (grow < M)
                w = ldPack4(Ap + (size_t)grow * 256 + k0 + k4 * 4);
            As[(k4 * 2 + 0) * AS_STRIDE + m] = w.x;
            As[(k4 * 2 + 1) * AS_STRIDE + m] = w.y;
        }
        // B tile: 32 k x 128 n -> [kp][n] packed (pair = rows 2kp, 2kp+1 same n)
#pragma unroll
        for (int it = 0; it < 2; it++) {
            int id = tid + it * 256;
            int n4 = id & 31;
            int kp = id >> 5;
            const float* r0 = Bw + (size_t)(k0 + kp * 2 + 0) * 256 + colBase + n4 * 4;
            const float* r1 = Bw + (size_t)(k0 + kp * 2 + 1) * 256 + colBase + n4 * 4;
            float4 va = *(const float4*)r0;
            float4 vb = *(const float4*)r1;
            uint4 w;
            __half2 h;
            h = __floats2half2_rn(va.x, vb.x); w.x = *(uint32_t*)&h;
            h = __floats2half2_rn(va.y, vb.y); w.y = *(uint32_t*)&h;
            h = __floats2half2_rn(va.z, vb.z); w.z = *(uint32_t*)&h;
            h = __floats2half2_rn(va.w, vb.w); w.w = *(uint32_t*)&h;
            *(uint4*)&Bs[kp * BS_STRIDE + n4 * 4] = w;
        }
        __syncthreads();

        // two k16 slabs per BK=32
#pragma unroll
        for (int s = 0; s < 2; s++) {
            int kp0 = s * 8;
            uint32_t a[2][4], b[8][2];
#pragma unroll
            for (int mt = 0; mt < 2; mt++) {
                int m = warpM * 32 + mt * 16 + g;
                a[mt][0] = As[(kp0 + t) * AS_STRIDE + m];
                a[mt][1] = As[(kp0 + t) * AS_STRIDE + m + 8];
                a[mt][2] = As[(kp0 + t + 4) * AS_STRIDE + m];
                a[mt][3] = As[(kp0 + t + 4) * AS_STRIDE + m + 8];
            }
#pragma unroll
            for (int nt = 0; nt < 8; nt++) {
                int n = warpN * 64 + nt * 8 + g;
                b[nt][0] = Bs[(kp0 + t) * BS_STRIDE + n];
                b[nt][1] = Bs[(kp0 + t + 4) * BS_STRIDE + n];
            }
#pragma unroll
            for (int mt = 0; mt < 2; mt++)
#pragma unroll
                for (int nt = 0; nt < 8; nt++) mma_f16(c[mt][nt], a[mt], b[nt]);
        }
        __syncthreads();
    }

    // epilogue: c0,c1 -> (row g, cols 2t,2t+1); c2,c3 -> (row g+8)
#pragma unroll
    for (int mt = 0; mt < 2; mt++) {
        int grow = rowBase + warpM * 32 + mt * 16 + g;
#pragma unroll
        for (int nt = 0; nt < 8; nt++) {
            int gcol = colBase + warpN * 64 + nt * 8 + t * 2;
            if (grow < M)
                *(__half2*)(g_bufT + (size_t)grow * 256 + gcol) =
                    __floats2half2_rn(c[mt][nt][0], c[mt][nt][1]);
            if (grow + 8 < M)
                *(__half2*)(g_bufT + (size_t)(grow + 8) * 256 + gcol) =
                    __floats2half2_rn(c[mt][nt][2], c[mt][nt][3]);
        }
    }
}

// ---------------- fp16 gather helper: accumulate one row into acc[8] ----------
__device__ __forceinline__ void acc_row(float acc[8], int s, float wt, int lane) {
    uint4 v = ((const uint4*)(g_bufT + (size_t)s * 256))[lane];
    const __half2* hp = (const __half2*)&v;
#pragma unroll
    for (int j = 0; j < 4; j++) {
        float2 f = __half22float2(hp[j]);
        acc[2 * j + 0] += wt * f.x;
        acc[2 * j + 1] += wt * f.y;
    }
}

// edge loop: unroll-8, all indices+weights fetched up front -> 8 independent
// LDG.128 gathers batched per iteration (compile-time unrolled)
__device__ __forceinline__ void agg_edges(float acc[8], int beg, int end,
                                          float disw, int lane) {
    int e = beg;
    for (; e + 8 <= end; e += 8) {
        int si[8];
        float wi[8];
#pragma unroll
        for (int j = 0; j < 8; j++) si[j] = g_csr_src[e + j];
#pragma unroll
        for (int j = 0; j < 8; j++) wi[j] = g_dis[si[j]] * disw;
#pragma unroll
        for (int j = 0; j < 8; j++) acc_row(acc, si[j], wi[j], lane);
    }
    for (; e + 4 <= end; e += 4) {
        int s0 = g_csr_src[e + 0], s1 = g_csr_src[e + 1];
        int s2 = g_csr_src[e + 2], s3 = g_csr_src[e + 3];
        float w0 = g_dis[s0] * disw, w1 = g_dis[s1] * disw;
        float w2 = g_dis[s2] * disw, w3 = g_dis[s3] * disw;
        acc_row(acc, s0, w0, lane);
        acc_row(acc, s1, w1, lane);
        acc_row(acc, s2, w2, lane);
        acc_row(acc, s3, w3, lane);
    }
    for (; e < end; e++) {
        int s = g_csr_src[e];
        acc_row(acc, s, g_dis[s] * disw, lane);
    }
}

// ---------------- aggregation (warp per node): g_bufH = relu(agg(g_bufT) + bias)
__global__ __launch_bounds__(256) void k_agg_relu(const float* __restrict__ bias) {
    int w = (blockIdx.x * blockDim.x + threadIdx.x) >> 5;
    int lane = threadIdx.x & 31;
    if (w >= N_NODES) return;
    int beg = g_offs[w], end = g_offs[w + 1];
    float disw = g_dis[w];
    float acc[8];
#pragma unroll
    for (int j = 0; j < 8; j++) acc[j] = 0.f;
    agg_edges(acc, beg, end, disw, lane);

    float4 b0 = ((const float4*)bias)[lane * 2];
    float4 b1 = ((const float4*)bias)[lane * 2 + 1];
    __half2 h[4];
    h[0] = __floats2half2_rn(fmaxf(acc[0] + b0.x, 0.f), fmaxf(acc[1] + b0.y, 0.f));
    h[1] = __floats2half2_rn(fmaxf(acc[2] + b0.z, 0.f), fmaxf(acc[3] + b0.w, 0.f));
    h[2] = __floats2half2_rn(fmaxf(acc[4] + b1.x, 0.f), fmaxf(acc[5] + b1.y, 0.f));
    h[3] = __floats2half2_rn(fmaxf(acc[6] + b1.z, 0.f), fmaxf(acc[7] + b1.w, 0.f));
    ((uint4*)(g_bufH + (size_t)w * 256))[lane] = *(uint4*)h;
}

// ---------------- agg layer 2 fused with final linear ------------------------
__global__ __launch_bounds__(256) void k_agg_final(const float* __restrict__ b2,
                                                   const float* __restrict__ Wl,
                                                   const float* __restrict__ bl,
                                                   float* __restrict__ out) {
    int w = (blockIdx.x * blockDim.x + threadIdx.x) >> 5;
    int lane = threadIdx.x & 31;
    if (w >= N_NODES) return;
    int beg = g_offs[w], end = g_offs[w + 1];
    float disw = g_dis[w];
    float acc[8];
#pragma unroll
    for (int j = 0; j < 8; j++) acc[j] = 0.f;
    agg_edges(acc, beg, end, disw, lane);

    float4 b0 = ((const float4*)b2)[lane * 2];
    float4 b1 = ((const float4*)b2)[lane * 2 + 1];
    float4 w0 = ((const float4*)Wl)[lane * 2];
    float4 w1 = ((const float4*)Wl)[lane * 2 + 1];
    float s =
        fmaxf(acc[0] + b0.x, 0.f) * w0.x + fmaxf(acc[1] + b0.y, 0.f) * w0.y +
        fmaxf(acc[2] + b0.z, 0.f) * w0.z + fmaxf(acc[3] + b0.w, 0.f) * w0.w +
        fmaxf(acc[4] + b1.x, 0.f) * w1.x + fmaxf(acc[5] + b1.y, 0.f) * w1.y +
        fmaxf(acc[6] + b1.z, 0.f) * w1.z + fmaxf(acc[7] + b1.w, 0.f) * w1.w;
#pragma unroll
    for (int o = 16; o > 0; o >>= 1) s += __shfl_xor_sync(0xFFFFFFFFu, s, o);
    if (lane == 0) out[w] = s + bl[0];
}

// ---------------- launch ----------------
extern "C" void kernel_launch(void* const* d_in, const int* in_sizes, int n_in,
                              void* d_out, int out_size) {
    const float* x  = (const float*)d_in[0];
    const int*   ei = (const int*)d_in[1];     // edge_index is int32 (JAX x64 disabled)
    const float* W1 = (const float*)d_in[2];
    const float* b1 = (const float*)d_in[3];
    const float* W2 = (const float*)d_in[4];
    const float* b2 = (const float*)d_in[5];
    const float* Wl = (const float*)d_in[6];
    const float* bl = (const float*)d_in[7];
    float* out = (float*)d_out;

    int E = in_sizes[1] / 2;
    int nblk = (N_NODES + SCAN_B - 1) / SCAN_B;           // 98
    int node_blocks = (N_NODES + 255) / 256;              // 391
    int agg_blocks = (N_NODES * 32 + 255) / 256;          // 12500 (warp per node)

    k_deg_init<<<node_blocks, 256>>>();

    // GEMM1 first half (rows [0, 50048)) overlapped with degree histogram
    k_gemm_aux<float, 1><<<AUX_BLOCKS + HALF_TILES * 2, 256>>>(
        x, W1, N_NODES, 0, HALF_TILES, ei, E, AUX_BLOCKS);

    // serial neck: offsets + dis + self-loops
    k_scan1<<<nblk, SCAN_B>>>();
    k_scan2<<<1, SCAN_B>>>(nblk);
    k_scan3<<<node_blocks, 256>>>();

    // GEMM1 second half (rows [50048, 100000)) overlapped with CSR fill
    k_gemm_aux<float, 2><<<AUX_BLOCKS + HALF_TILES * 2, 256>>>(
        x, W1, N_NODES, HALF_TILES, HALF_TILES, ei, E, AUX_BLOCKS);

    // layer 1 aggregation: H = relu(agg(T) + b1)
    k_agg_relu<<<agg_blocks, 256>>>(b1);

    // layer 2: T = H @ W2 ; out = relu(agg(T) + b2) @ Wl + bl   (fused)
    k_gemm_aux<__half, 0><<<FULL_TILES * 2, 256>>>(
        (const __half*)nullptr, W2, N_NODES, 0, FULL_TILES, nullptr, 0, 0);
    k_agg_final<<<agg_blocks, 256>>>(b2, Wl, bl, out);
}

// round 13
// speedup vs baseline: 1.2285x; 1.0131x over previous
#include <cuda_runtime.h>
#include <cuda_fp16.h>
#include <cuda_bf16.h>
#include <cstdint>

#define N_NODES 100000
#define C_DIM   256
#define CSR_CAP 3400000
#define SCAN_B  1024

// GEMM tiling (fp16 HMMA m16n8k16; smem holds k-PAIRS packed in 32-bit words)
#define BM 128
#define BN 128
#define BK 32
#define KP (BK / 2)
#define AS_STRIDE 129    // words per kp-row of As (odd -> conflict-free)
#define BS_STRIDE 132    // words per kp-row of Bs

#define AUX_BLOCKS 512
#define HALF_TILES 391   // row tiles per GEMM half (391*128 = 50048)
#define HALF_ROWS  50048

// ---------------- device scratch (no allocations allowed) ----------------
__device__ int    g_deg[N_NODES];
__device__ int    g_offs[N_NODES + 1];
__device__ int    g_cursor[N_NODES];
__device__ float  g_dis[N_NODES];
__device__ int    g_blockSums[SCAN_B];
__device__ int    g_csr_src[CSR_CAP];
__device__ __half g_bufT[(size_t)N_NODES * C_DIM];   // layer-1 transformed feats
__device__ __half g_bufT2[(size_t)N_NODES * C_DIM];  // layer-2 transformed feats (dis-prescaled)
__device__ __half g_bufH[(size_t)N_NODES * C_DIM];   // layer-1 output (fp16)

// ---------------- degree init ----------------
__global__ void k_deg_init() {
    int i = blockIdx.x * blockDim.x + threadIdx.x;
    if (i < N_NODES) g_deg[i] = 1;   // self-loop
}

// ---------------- exclusive scan of degrees -> CSR row offsets ----------------
__global__ void k_scan1() {
    __shared__ int s[SCAN_B];
    int tid = threadIdx.x;
    int i = blockIdx.x * SCAN_B + tid;
    int v = (i < N_NODES) ? g_deg[i] : 0;
    s[tid] = v;
    __syncthreads();
#pragma unroll
    for (int off = 1; off < SCAN_B; off <<= 1) {
        int a = (tid >= off) ? s[tid - off] : 0;
        __syncthreads();
        s[tid] += a;
        __syncthreads();
    }
    if (i < N_NODES) g_offs[i] = s[tid] - v;
    if (tid == SCAN_B - 1) g_blockSums[blockIdx.x] = s[tid];
}

__global__ void k_scan2(int nblk) {
    __shared__ int s[SCAN_B];
    int tid = threadIdx.x;
    int v = (tid < nblk) ? g_blockSums[tid] : 0;
    s[tid] = v;
    __syncthreads();
#pragma unroll
    for (int off = 1; off < SCAN_B; off <<= 1) {
        int a = (tid >= off) ? s[tid - off] : 0;
        __syncthreads();
        s[tid] += a;
        __syncthreads();
    }
    if (tid < nblk) g_blockSums[tid] = s[tid] - v;
}

// scan finalize + deg_inv_sqrt + deterministic self-loop in each row's LAST slot
__global__ void k_scan3() {
    int i = blockIdx.x * blockDim.x + threadIdx.x;
    if (i < N_NODES) {
        int deg = g_deg[i];
        int e = g_offs[i] + g_blockSums[i >> 10];
        g_offs[i] = e;
        g_cursor[i] = e;
        g_dis[i] = rsqrtf((float)deg);
        g_csr_src[e + deg - 1] = i;            // self-loop; weight dis^2 falls out
        if (i == N_NODES - 1) g_offs[N_NODES] = e + deg;
    }
}

// ---------------- fp16 HMMA helpers ----------------
__device__ __forceinline__ void mma_f16(float c[4], const uint32_t a[4],
                                        const uint32_t b[2]) {
    asm volatile(
        "mma.sync.aligned.m16n8k16.row.col.f32.f16.f16.f32 "
        "{%0,%1,%2,%3}, {%4,%5,%6,%7}, {%8,%9}, {%0,%1,%2,%3};"
        : "+f"(c[0]), "+f"(c[1]), "+f"(c[2]), "+f"(c[3])
        : "r"(a[0]), "r"(a[1]), "r"(a[2]), "r"(a[3]), "r"(b[0]), "r"(b[1]));
}

__device__ __forceinline__ uint2 ldPack4(const float* p) {
    float4 v = *(const float4*)p;
    uint2 w;
    __half2 h0 = __floats2half2_rn(v.x, v.y);
    __half2 h1 = __floats2half2_rn(v.z, v.w);
    w.x = *(uint32_t*)&h0;
    w.y = *(uint32_t*)&h1;
    return w;
}
__device__ __forceinline__ uint2 ldPack4(const __half* p) {
    return *(const uint2*)p;     // already fp16, k-contiguous
}

// ---------------- fp16 tensor-core GEMM (+ optional fused aux CTAs) ----------
// AUX: 0 = none, 1 = degree histogram, 2 = CSR fill (aux CTAs at low block idx)
// prescale != 0: multiply output row r by g_dis[r] (for layer-2 weight folding)
template <typename TA, int AUX>
__global__ __launch_bounds__(256, 2) void k_gemm_aux(const TA* __restrict__ A,
                                                     const float* __restrict__ Bw,
                                                     __half* __restrict__ outT,
                                                     int M, int rowTileOff,
                                                     int nRowTiles,
                                                     const int* __restrict__ ei,
                                                     int E, int auxBlocks,
                                                     int prescale) {
    if (AUX != 0 && (int)blockIdx.x < auxBlocks) {
        int t = blockIdx.x * 256 + threadIdx.x;
        int stride = auxBlocks * 256;
        if (AUX == 1) {
            for (int e = t; e < E; e += stride)
                atomicAdd(&g_deg[ei[E + e]], 1);
        } else {
            for (int e = t; e < E; e += stride) {
                int s = ei[e];
                int d = ei[E + e];
                int pos = atomicAdd(&g_cursor[d], 1);
                g_csr_src[pos] = s;
            }
        }
        return;
    }

    __shared__ uint32_t As[KP * AS_STRIDE];     // [kp][m] packed half2 (k-pairs)
    __shared__ uint32_t Bs[KP * BS_STRIDE];     // [kp][n] packed half2 (k-pairs)

    int tile = blockIdx.x - auxBlocks;
    int rowBase = (rowTileOff + tile % nRowTiles) * BM;
    int colBase = (tile / nRowTiles) * BN;

    int tid = threadIdx.x;
    int lane = tid & 31;
    int warp = tid >> 5;
    int warpM = warp & 3;
    int warpN = warp >> 2;
    int g = lane >> 2;
    int t = lane & 3;

    float c[2][8][4];
#pragma unroll
    for (int mt = 0; mt < 2; mt++)
#pragma unroll
        for (int nt = 0; nt < 8; nt++)
#pragma unroll
            for (int j = 0; j < 4; j++) c[mt][nt][j] = 0.f;

    for (int k0 = 0; k0 < 256; k0 += BK) {
#pragma unroll
        for (int it = 0; it < 4; it++) {
            int id = tid + it * 256;
            int k4 = id & 7;
            int m = id >> 3;
            int grow = rowBase + m;
            uint2 w = make_uint2(0u, 0u);
            if (grow < M)
                w = ldPack4(A + (size_t)grow * 256 + k0 + k4 * 4);
            As[(k4 * 2 + 0) * AS_STRIDE + m] = w.x;
            As[(k4 * 2 + 1) * AS_STRIDE + m] = w.y;
        }
#pragma unroll
        for (int it = 0; it < 2; it++) {
            int id = tid + it * 256;
            int n4 = id & 31;
            int kp = id >> 5;
            const float* r0 = Bw + (size_t)(k0 + kp * 2 + 0) * 256 + colBase + n4 * 4;
            const float* r1 = Bw + (size_t)(k0 + kp * 2 + 1) * 256 + colBase + n4 * 4;
            float4 va = *(const float4*)r0;
            float4 vb = *(const float4*)r1;
            uint4 w;
            __half2 h;
            h = __floats2half2_rn(va.x, vb.x); w.x = *(uint32_t*)&h;
            h = __floats2half2_rn(va.y, vb.y); w.y = *(uint32_t*)&h;
            h = __floats2half2_rn(va.z, vb.z); w.z = *(uint32_t*)&h;
            h = __floats2half2_rn(va.w, vb.w); w.w = *(uint32_t*)&h;
            *(uint4*)&Bs[kp * BS_STRIDE + n4 * 4] = w;
        }
        __syncthreads();

#pragma unroll
        for (int s = 0; s < 2; s++) {
            int kp0 = s * 8;
            uint32_t a[2][4], b[8][2];
#pragma unroll
            for (int mt = 0; mt < 2; mt++) {
                int m = warpM * 32 + mt * 16 + g;
                a[mt][0] = As[(kp0 + t) * AS_STRIDE + m];
                a[mt][1] = As[(kp0 + t) * AS_STRIDE + m + 8];
                a[mt][2] = As[(kp0 + t + 4) * AS_STRIDE + m];
                a[mt][3] = As[(kp0 + t + 4) * AS_STRIDE + m + 8];
            }
#pragma unroll
            for (int nt = 0; nt < 8; nt++) {
                int n = warpN * 64 + nt * 8 + g;
                b[nt][0] = Bs[(kp0 + t) * BS_STRIDE + n];
                b[nt][1] = Bs[(kp0 + t + 4) * BS_STRIDE + n];
            }
#pragma unroll
            for (int mt = 0; mt < 2; mt++)
#pragma unroll
                for (int nt = 0; nt < 8; nt++) mma_f16(c[mt][nt], a[mt], b[nt]);
        }
        __syncthreads();
    }

#pragma unroll
    for (int mt = 0; mt < 2; mt++) {
        int grow = rowBase + warpM * 32 + mt * 16 + g;
        float s0 = 1.f, s1 = 1.f;
        if (prescale) {
            if (grow < M) s0 = g_dis[grow];
            if (grow + 8 < M) s1 = g_dis[grow + 8];
        }
#pragma unroll
        for (int nt = 0; nt < 8; nt++) {
            int gcol = colBase + warpN * 64 + nt * 8 + t * 2;
            if (grow < M)
                *(__half2*)(outT + (size_t)grow * 256 + gcol) =
                    __floats2half2_rn(c[mt][nt][0] * s0, c[mt][nt][1] * s0);
            if (grow + 8 < M)
                *(__half2*)(outT + (size_t)(grow + 8) * 256 + gcol) =
                    __floats2half2_rn(c[mt][nt][2] * s1, c[mt][nt][3] * s1);
        }
    }
}

// ---------------- fp16 gather helpers ----------------
__device__ __forceinline__ void acc_row(float acc[8], const __half* __restrict__ buf,
                                        int s, float wt, int lane) {
    uint4 v = ((const uint4*)(buf + (size_t)s * 256))[lane];
    const __half2* hp = (const __half2*)&v;
#pragma unroll
    for (int j = 0; j < 4; j++) {
        float2 f = __half22float2(hp[j]);
        acc[2 * j + 0] += wt * f.x;
        acc[2 * j + 1] += wt * f.y;
    }
}

__device__ __forceinline__ void acc_row_add(float acc[8], const __half* __restrict__ buf,
                                            int s, int lane) {
    uint4 v = ((const uint4*)(buf + (size_t)s * 256))[lane];
    const __half2* hp = (const __half2*)&v;
#pragma unroll
    for (int j = 0; j < 4; j++) {
        float2 f = __half22float2(hp[j]);
        acc[2 * j + 0] += f.x;
        acc[2 * j + 1] += f.y;
    }
}

// weighted edge loop (layer 1): unroll-8, indices+weights batched up front
__device__ __forceinline__ void agg_edges(float acc[8], const __half* __restrict__ buf,
                                          int beg, int end, float disw, int lane) {
    int e = beg;
    for (; e + 8 <= end; e += 8) {
        int si[8];
        float wi[8];
#pragma unroll
        for (int j = 0; j < 8; j++) si[j] = g_csr_src[e + j];
#pragma unroll
        for (int j = 0; j < 8; j++) wi[j] = g_dis[si[j]] * disw;
#pragma unroll
        for (int j = 0; j < 8; j++) acc_row(acc, buf, si[j], wi[j], lane);
    }
    for (; e + 4 <= end; e += 4) {
        int s0 = g_csr_src[e + 0], s1 = g_csr_src[e + 1];
        int s2 = g_csr_src[e + 2], s3 = g_csr_src[e + 3];
        float w0 = g_dis[s0] * disw, w1 = g_dis[s1] * disw;
        float w2 = g_dis[s2] * disw, w3 = g_dis[s3] * disw;
        acc_row(acc, buf, s0, w0, lane);
        acc_row(acc, buf, s1, w1, lane);
        acc_row(acc, buf, s2, w2, lane);
        acc_row(acc, buf, s3, w3, lane);
    }
    for (; e < end; e++) {
        int s = g_csr_src[e];
        acc_row(acc, buf, s, g_dis[s] * disw, lane);
    }
}

// unweighted edge loop (layer 2; weights pre-folded into g_bufT2 rows)
__device__ __forceinline__ void agg_edges_add(float acc[8], const __half* __restrict__ buf,
                                              int beg, int end, int lane) {
    int e = beg;
    for (; e + 8 <= end; e += 8) {
        int si[8];
#pragma unroll
        for (int j = 0; j < 8; j++) si[j] = g_csr_src[e + j];
#pragma unroll
        for (int j = 0; j < 8; j++) acc_row_add(acc, buf, si[j], lane);
    }
    for (; e + 4 <= end; e += 4) {
        int s0 = g_csr_src[e + 0], s1 = g_csr_src[e + 1];
        int s2 = g_csr_src[e + 2], s3 = g_csr_src[e + 3];
        acc_row_add(acc, buf, s0, lane);
        acc_row_add(acc, buf, s1, lane);
        acc_row_add(acc, buf, s2, lane);
        acc_row_add(acc, buf, s3, lane);
    }
    for (; e < end; e++) acc_row_add(acc, buf, g_csr_src[e], lane);
}

// ---------------- layer-1 aggregation over a node range ----------------------
__global__ __launch_bounds__(256) void k_agg_relu(const float* __restrict__ bias,
                                                  int nodeOff, int nodeEnd) {
    int w = nodeOff + ((blockIdx.x * blockDim.x + threadIdx.x) >> 5);
    int lane = threadIdx.x & 31;
    if (w >= nodeEnd) return;
    int beg = g_offs[w], end = g_offs[w + 1];
    float disw = g_dis[w];
    float acc[8];
#pragma unroll
    for (int j = 0; j < 8; j++) acc[j] = 0.f;
    agg_edges(acc, g_bufT, beg, end, disw, lane);

    float4 b0 = ((const float4*)bias)[lane * 2];
    float4 b1 = ((const float4*)bias)[lane * 2 + 1];
    __half2 h[4];
    h[0] = __floats2half2_rn(fmaxf(acc[0] + b0.x, 0.f), fmaxf(acc[1] + b0.y, 0.f));
    h[1] = __floats2half2_rn(fmaxf(acc[2] + b0.z, 0.f), fmaxf(acc[3] + b0.w, 0.f));
    h[2] = __floats2half2_rn(fmaxf(acc[4] + b1.x, 0.f), fmaxf(acc[5] + b1.y, 0.f));
    h[3] = __floats2half2_rn(fmaxf(acc[6] + b1.z, 0.f), fmaxf(acc[7] + b1.w, 0.f));
    ((uint4*)(g_bufH + (size_t)w * 256))[lane] = *(uint4*)h;
}

// ---------------- agg layer 2 (unweighted sum of prescaled rows) + head ------
__global__ __launch_bounds__(256) void k_agg_final(const float* __restrict__ b2,
                                                   const float* __restrict__ Wl,
                                                   const float* __restrict__ bl,
                                                   float* __restrict__ out) {
    int w = (blockIdx.x * blockDim.x + threadIdx.x) >> 5;
    int lane = threadIdx.x & 31;
    if (w >= N_NODES) return;
    int beg = g_offs[w], end = g_offs[w + 1];
    float disw = g_dis[w];
    float acc[8];
#pragma unroll
    for (int j = 0; j < 8; j++) acc[j] = 0.f;
    agg_edges_add(acc, g_bufT2, beg, end, lane);
#pragma unroll
    for (int j = 0; j < 8; j++) acc[j] *= disw;

    float4 b0 = ((const float4*)b2)[lane * 2];
    float4 b1 = ((const float4*)b2)[lane * 2 + 1];
    float4 w0 = ((const float4*)Wl)[lane * 2];
    float4 w1 = ((const float4*)Wl)[lane * 2 + 1];
    float s =
        fmaxf(acc[0] + b0.x, 0.f) * w0.x + fmaxf(acc[1] + b0.y, 0.f) * w0.y +
        fmaxf(acc[2] + b0.z, 0.f) * w0.z + fmaxf(acc[3] + b0.w, 0.f) * w0.w +
        fmaxf(acc[4] + b1.x, 0.f) * w1.x + fmaxf(acc[5] + b1.y, 0.f) * w1.y +
        fmaxf(acc[6] + b1.z, 0.f) * w1.z + fmaxf(acc[7] + b1.w, 0.f) * w1.w;
#pragma unroll
    for (int o = 16; o > 0; o >>= 1) s += __shfl_xor_sync(0xFFFFFFFFu, s, o);
    if (lane == 0) out[w] = s + bl[0];
}

// ---------------- launch ----------------
extern "C" void kernel_launch(void* const* d_in, const int* in_sizes, int n_in,
                              void* d_out, int out_size) {
    const float* x  = (const float*)d_in[0];
    const int*   ei = (const int*)d_in[1];     // edge_index is int32 (JAX x64 disabled)
    const float* W1 = (const float*)d_in[2];
    const float* b1 = (const float*)d_in[3];
    const float* W2 = (const float*)d_in[4];
    const float* b2 = (const float*)d_in[5];
    const float* Wl = (const float*)d_in[6];
    const float* bl = (const float*)d_in[7];
    float* out = (float*)d_out;

    // one-time host-side setup (correctness run happens before graph capture;
    // identical GPU work is issued on every call)
    static bool inited = false;
    static cudaStream_t sB;
    static cudaEvent_t evF, evJ;
    static __half *pT, *pT2, *pH;
    if (!inited) {
        cudaStreamCreate(&sB);
        cudaEventCreateWithFlags(&evF, cudaEventDisableTiming);
        cudaEventCreateWithFlags(&evJ, cudaEventDisableTiming);
        void* p;
        cudaGetSymbolAddress(&p, g_bufT);  pT  = (__half*)p;
        cudaGetSymbolAddress(&p, g_bufT2); pT2 = (__half*)p;
        cudaGetSymbolAddress(&p, g_bufH);  pH  = (__half*)p;
        inited = true;
    }

    int E = in_sizes[1] / 2;
    int nblk = (N_NODES + SCAN_B - 1) / SCAN_B;           // 98
    int node_blocks = (N_NODES + 255) / 256;              // 391
    int agg_blocks = (N_NODES * 32 + 255) / 256;          // 12500
    int agg1a_blocks = (HALF_ROWS * 32 + 255) / 256;              // 6256
    int agg1b_blocks = ((N_NODES - HALF_ROWS) * 32 + 255) / 256;  // 6244

    k_deg_init<<<node_blocks, 256>>>();

    // GEMM1 first half (rows [0, 50048)) overlapped with degree histogram
    k_gemm_aux<float, 1><<<AUX_BLOCKS + HALF_TILES * 2, 256>>>(
        x, W1, pT, N_NODES, 0, HALF_TILES, ei, E, AUX_BLOCKS, 0);

    // serial neck: offsets + dis + self-loops
    k_scan1<<<nblk, SCAN_B>>>();
    k_scan2<<<1, SCAN_B>>>(nblk);
    k_scan3<<<node_blocks, 256>>>();

    // GEMM1 second half (rows [50048, 100000)) overlapped with CSR fill
    k_gemm_aux<float, 2><<<AUX_BLOCKS + HALF_TILES * 2, 256>>>(
        x, W1, pT, N_NODES, HALF_TILES, HALF_TILES, ei, E, AUX_BLOCKS, 0);

    // agg1 first half on the capture stream
    k_agg_relu<<<agg1a_blocks, 256>>>(b1, 0, HALF_ROWS);

    // fork: GEMM2 rows [0, 50048) (reads bufH[0,50048), writes bufT2, prescaled)
    //       runs concurrently with agg1 second half (reads bufT, writes bufH)
    cudaEventRecord(evF, 0);
    cudaStreamWaitEvent(sB, evF, 0);
    k_gemm_aux<__half, 0><<<HALF_TILES * 2, 256, 0, sB>>>(
        pH, W2, pT2, N_NODES, 0, HALF_TILES, nullptr, 0, 0, 1);
    cudaEventRecord(evJ, sB);

    k_agg_relu<<<agg1b_blocks, 256>>>(b1, HALF_ROWS, N_NODES);

    // join, then GEMM2 second half
    cudaStreamWaitEvent((cudaStream_t)0, evJ, 0);
    k_gemm_aux<__half, 0><<<HALF_TILES * 2, 256>>>(
        pH, W2, pT2, N_NODES, HALF_TILES, HALF_TILES, nullptr, 0, 0, 1);

    // layer-2 aggregation (unweighted; weights folded into bufT2) + head
    k_agg_final<<<agg_blocks, 256>>>(b2, Wl, bl, out);
}

// round 14
// speedup vs baseline: 1.2450x; 1.0134x over previous
#include <cuda_runtime.h>
#include <cuda_fp16.h>
#include <cuda_bf16.h>
#include <cstdint>

#define N_NODES 100000
#define C_DIM   256
#define CSR_CAP 3400000
#define SCAN_B  1024

// GEMM tiling (fp16 HMMA m16n8k16; smem holds k-PAIRS packed in 32-bit words)
#define BM 128
#define BN 128
#define BK 32
#define KP (BK / 2)
#define AS_STRIDE 129    // words per kp-row of As (odd -> conflict-free)
#define BS_STRIDE 132    // words per kp-row of Bs

#define AUX_BLOCKS 512
#define HALF_TILES 391   // row tiles per GEMM half (391*128 = 50048)
#define HALF_ROWS  50048

// ---------------- device scratch (no allocations allowed) ----------------
__device__ int    g_deg[N_NODES];          // raw incoming-edge counts (no self-loop)
__device__ int    g_offs[N_NODES + 1];
__device__ int    g_cursor[N_NODES];
__device__ float  g_dis[N_NODES];
__device__ int    g_blockSums[SCAN_B];
__device__ int    g_csr_src[CSR_CAP];
__device__ __half g_bufT[(size_t)N_NODES * C_DIM];   // layer-1 transformed feats
__device__ __half g_bufT2[(size_t)N_NODES * C_DIM];  // layer-2 feats (dis-prescaled)
__device__ __half g_bufH[(size_t)N_NODES * C_DIM];   // layer-1 output (fp16)

// ---------------- exclusive scan of (deg+1) -> CSR row offsets ----------------
__global__ void k_scan1() {
    __shared__ int s[SCAN_B];
    int tid = threadIdx.x;
    int i = blockIdx.x * SCAN_B + tid;
    int v = (i < N_NODES) ? g_deg[i] + 1 : 0;   // +1 = self-loop
    s[tid] = v;
    __syncthreads();
#pragma unroll
    for (int off = 1; off < SCAN_B; off <<= 1) {
        int a = (tid >= off) ? s[tid - off] : 0;
        __syncthreads();
        s[tid] += a;
        __syncthreads();
    }
    if (i < N_NODES) g_offs[i] = s[tid] - v;
    if (tid == SCAN_B - 1) g_blockSums[blockIdx.x] = s[tid];
}

__global__ void k_scan2(int nblk) {
    __shared__ int s[SCAN_B];
    int tid = threadIdx.x;
    int v = (tid < nblk) ? g_blockSums[tid] : 0;
    s[tid] = v;
    __syncthreads();
#pragma unroll
    for (int off = 1; off < SCAN_B; off <<= 1) {
        int a = (tid >= off) ? s[tid - off] : 0;
        __syncthreads();
        s[tid] += a;
        __syncthreads();
    }
    if (tid < nblk) g_blockSums[tid] = s[tid] - v;
}

// scan finalize + deg_inv_sqrt + deterministic self-loop in each row's LAST slot
__global__ void k_scan3() {
    int i = blockIdx.x * blockDim.x + threadIdx.x;
    if (i < N_NODES) {
        int deg = g_deg[i] + 1;                // incl. self-loop
        int e = g_offs[i] + g_blockSums[i >> 10];
        g_offs[i] = e;
        g_cursor[i] = e;
        g_dis[i] = rsqrtf((float)deg);
        g_csr_src[e + deg - 1] = i;            // self-loop; weight dis^2 falls out
        if (i == N_NODES - 1) g_offs[N_NODES] = e + deg;
    }
}

// ---------------- standalone CSR fill (src only) ------------------------------
__global__ void k_fill(const int* __restrict__ ei, int E) {
    for (int e = blockIdx.x * blockDim.x + threadIdx.x; e < E;
         e += gridDim.x * blockDim.x) {
        int s = ei[e];
        int d = ei[E + e];
        int pos = atomicAdd(&g_cursor[d], 1);
        g_csr_src[pos] = s;
    }
}

// ---------------- fp16 HMMA helpers ----------------
__device__ __forceinline__ void mma_f16(float c[4], const uint32_t a[4],
                                        const uint32_t b[2]) {
    asm volatile(
        "mma.sync.aligned.m16n8k16.row.col.f32.f16.f16.f32 "
        "{%0,%1,%2,%3}, {%4,%5,%6,%7}, {%8,%9}, {%0,%1,%2,%3};"
        : "+f"(c[0]), "+f"(c[1]), "+f"(c[2]), "+f"(c[3])
        : "r"(a[0]), "r"(a[1]), "r"(a[2]), "r"(a[3]), "r"(b[0]), "r"(b[1]));
}

__device__ __forceinline__ uint2 ldPack4(const float* p) {
    float4 v = *(const float4*)p;
    uint2 w;
    __half2 h0 = __floats2half2_rn(v.x, v.y);
    __half2 h1 = __floats2half2_rn(v.z, v.w);
    w.x = *(uint32_t*)&h0;
    w.y = *(uint32_t*)&h1;
    return w;
}
__device__ __forceinline__ uint2 ldPack4(const __half* p) {
    return *(const uint2*)p;     // already fp16, k-contiguous
}

// ---------------- fp16 tensor-core GEMM (+ optional fused aux CTAs) ----------
// AUX: 0 = none, 1 = degree histogram (aux CTAs at low block idx)
// prescale != 0: multiply output row r by g_dis[r] (layer-2 weight folding)
template <typename TA, int AUX>
__global__ __launch_bounds__(256, 2) void k_gemm_aux(const TA* __restrict__ A,
                                                     const float* __restrict__ Bw,
                                                     __half* __restrict__ outT,
                                                     int M, int rowTileOff,
                                                     int nRowTiles,
                                                     const int* __restrict__ ei,
                                                     int E, int auxBlocks,
                                                     int prescale) {
    if (AUX != 0 && (int)blockIdx.x < auxBlocks) {
        int t = blockIdx.x * 256 + threadIdx.x;
        int stride = auxBlocks * 256;
        for (int e = t; e < E; e += stride)
            atomicAdd(&g_deg[ei[E + e]], 1);
        return;
    }

    __shared__ uint32_t As[KP * AS_STRIDE];     // [kp][m] packed half2 (k-pairs)
    __shared__ uint32_t Bs[KP * BS_STRIDE];     // [kp][n] packed half2 (k-pairs)

    int tile = blockIdx.x - auxBlocks;
    int rowBase = (rowTileOff + tile % nRowTiles) * BM;
    int colBase = (tile / nRowTiles) * BN;

    int tid = threadIdx.x;
    int lane = tid & 31;
    int warp = tid >> 5;
    int warpM = warp & 3;
    int warpN = warp >> 2;
    int g = lane >> 2;
    int t = lane & 3;

    float c[2][8][4];
#pragma unroll
    for (int mt = 0; mt < 2; mt++)
#pragma unroll
        for (int nt = 0; nt < 8; nt++)
#pragma unroll
            for (int j = 0; j < 4; j++) c[mt][nt][j] = 0.f;

    for (int k0 = 0; k0 < 256; k0 += BK) {
#pragma unroll
        for (int it = 0; it < 4; it++) {
            int id = tid + it * 256;
            int k4 = id & 7;
            int m = id >> 3;
            int grow = rowBase + m;
            uint2 w = make_uint2(0u, 0u);
            if (grow < M)
                w = ldPack4(A + (size_t)grow * 256 + k0 + k4 * 4);
            As[(k4 * 2 + 0) * AS_STRIDE + m] = w.x;
            As[(k4 * 2 + 1) * AS_STRIDE + m] = w.y;
        }
#pragma unroll
        for (int it = 0; it < 2; it++) {
            int id = tid + it * 256;
            int n4 = id & 31;
            int kp = id >> 5;
            const float* r0 = Bw + (size_t)(k0 + kp * 2 + 0) * 256 + colBase + n4 * 4;
            const float* r1 = Bw + (size_t)(k0 + kp * 2 + 1) * 256 + colBase + n4 * 4;
            float4 va = *(const float4*)r0;
            float4 vb = *(const float4*)r1;
            uint4 w;
            __half2 h;
            h = __floats2half2_rn(va.x, vb.x); w.x = *(uint32_t*)&h;
            h = __floats2half2_rn(va.y, vb.y); w.y = *(uint32_t*)&h;
            h = __floats2half2_rn(va.z, vb.z); w.z = *(uint32_t*)&h;
            h = __floats2half2_rn(va.w, vb.w); w.w = *(uint32_t*)&h;
            *(uint4*)&Bs[kp * BS_STRIDE + n4 * 4] = w;
        }
        __syncthreads();

#pragma unroll
        for (int s = 0; s < 2; s++) {
            int kp0 = s * 8;
            uint32_t a[2][4], b[8][2];
#pragma unroll
            for (int mt = 0; mt < 2; mt++) {
                int m = warpM * 32 + mt * 16 + g;
                a[mt][0] = As[(kp0 + t) * AS_STRIDE + m];
                a[mt][1] = As[(kp0 + t) * AS_STRIDE + m + 8];
                a[mt][2] = As[(kp0 + t + 4) * AS_STRIDE + m];
                a[mt][3] = As[(kp0 + t + 4) * AS_STRIDE + m + 8];
            }
#pragma unroll
            for (int nt = 0; nt < 8; nt++) {
                int n = warpN * 64 + nt * 8 + g;
                b[nt][0] = Bs[(kp0 + t) * BS_STRIDE + n];
                b[nt][1] = Bs[(kp0 + t + 4) * BS_STRIDE + n];
            }
#pragma unroll
            for (int mt = 0; mt < 2; mt++)
#pragma unroll
                for (int nt = 0; nt < 8; nt++) mma_f16(c[mt][nt], a[mt], b[nt]);
        }
        __syncthreads();
    }

#pragma unroll
    for (int mt = 0; mt < 2; mt++) {
        int grow = rowBase + warpM * 32 + mt * 16 + g;
        float s0 = 1.f, s1 = 1.f;
        if (prescale) {
            if (grow < M) s0 = g_dis[grow];
            if (grow + 8 < M) s1 = g_dis[grow + 8];
        }
#pragma unroll
        for (int nt = 0; nt < 8; nt++) {
            int gcol = colBase + warpN * 64 + nt * 8 + t * 2;
            if (grow < M)
                *(__half2*)(outT + (size_t)grow * 256 + gcol) =
                    __floats2half2_rn(c[mt][nt][0] * s0, c[mt][nt][1] * s0);
            if (grow + 8 < M)
                *(__half2*)(outT + (size_t)(grow + 8) * 256 + gcol) =
                    __floats2half2_rn(c[mt][nt][2] * s1, c[mt][nt][3] * s1);
        }
    }
}

// ---------------- fp16 gather helpers ----------------
__device__ __forceinline__ void acc_row(float acc[8], const __half* __restrict__ buf,
                                        int s, float wt, int lane) {
    uint4 v = ((const uint4*)(buf + (size_t)s * 256))[lane];
    const __half2* hp = (const __half2*)&v;
#pragma unroll
    for (int j = 0; j < 4; j++) {
        float2 f = __half22float2(hp[j]);
        acc[2 * j + 0] += wt * f.x;
        acc[2 * j + 1] += wt * f.y;
    }
}

__device__ __forceinline__ void acc_row_add(float acc[8], const __half* __restrict__ buf,
                                            int s, int lane) {
    uint4 v = ((const uint4*)(buf + (size_t)s * 256))[lane];
    const __half2* hp = (const __half2*)&v;
#pragma unroll
    for (int j = 0; j < 4; j++) {
        float2 f = __half22float2(hp[j]);
        acc[2 * j + 0] += f.x;
        acc[2 * j + 1] += f.y;
    }
}

// weighted edge loop (layer 1): unroll-8, indices+weights batched up front
__device__ __forceinline__ void agg_edges(float acc[8], const __half* __restrict__ buf,
                                          int beg, int end, float disw, int lane) {
    int e = beg;
    for (; e + 8 <= end; e += 8) {
        int si[8];
        float wi[8];
#pragma unroll
        for (int j = 0; j < 8; j++) si[j] = g_csr_src[e + j];
#pragma unroll
        for (int j = 0; j < 8; j++) wi[j] = g_dis[si[j]] * disw;
#pragma unroll
        for (int j = 0; j < 8; j++) acc_row(acc, buf, si[j], wi[j], lane);
    }
    for (; e + 4 <= end; e += 4) {
        int s0 = g_csr_src[e + 0], s1 = g_csr_src[e + 1];
        int s2 = g_csr_src[e + 2], s3 = g_csr_src[e + 3];
        float w0 = g_dis[s0] * disw, w1 = g_dis[s1] * disw;
        float w2 = g_dis[s2] * disw, w3 = g_dis[s3] * disw;
        acc_row(acc, buf, s0, w0, lane);
        acc_row(acc, buf, s1, w1, lane);
        acc_row(acc, buf, s2, w2, lane);
        acc_row(acc, buf, s3, w3, lane);
    }
    for (; e < end; e++) {
        int s = g_csr_src[e];
        acc_row(acc, buf, s, g_dis[s] * disw, lane);
    }
}

// unweighted edge loop (layer 2; weights pre-folded into g_bufT2 rows)
__device__ __forceinline__ void agg_edges_add(float acc[8], const __half* __restrict__ buf,
                                              int beg, int end, int lane) {
    int e = beg;
    for (; e + 8 <= end; e += 8) {
        int si[8];
#pragma unroll
        for (int j = 0; j < 8; j++) si[j] = g_csr_src[e + j];
#pragma unroll
        for (int j = 0; j < 8; j++) acc_row_add(acc, buf, si[j], lane);
    }
    for (; e + 4 <= end; e += 4) {
        int s0 = g_csr_src[e + 0], s1 = g_csr_src[e + 1];
        int s2 = g_csr_src[e + 2], s3 = g_csr_src[e + 3];
        acc_row_add(acc, buf, s0, lane);
        acc_row_add(acc, buf, s1, lane);
        acc_row_add(acc, buf, s2, lane);
        acc_row_add(acc, buf, s3, lane);
    }
    for (; e < end; e++) acc_row_add(acc, buf, g_csr_src[e], lane);
}

// ---------------- layer-1 aggregation over a node range ----------------------
__global__ __launch_bounds__(256) void k_agg_relu(const float* __restrict__ bias,
                                                  int nodeOff, int nodeEnd) {
    int w = nodeOff + ((blockIdx.x * blockDim.x + threadIdx.x) >> 5);
    int lane = threadIdx.x & 31;
    if (w >= nodeEnd) return;
    int beg = g_offs[w], end = g_offs[w + 1];
    float disw = g_dis[w];
    float acc[8];
#pragma unroll
    for (int j = 0; j < 8; j++) acc[j] = 0.f;
    agg_edges(acc, g_bufT, beg, end, disw, lane);

    float4 b0 = ((const float4*)bias)[lane * 2];
    float4 b1 = ((const float4*)bias)[lane * 2 + 1];
    __half2 h[4];
    h[0] = __floats2half2_rn(fmaxf(acc[0] + b0.x, 0.f), fmaxf(acc[1] + b0.y, 0.f));
    h[1] = __floats2half2_rn(fmaxf(acc[2] + b0.z, 0.f), fmaxf(acc[3] + b0.w, 0.f));
    h[2] = __floats2half2_rn(fmaxf(acc[4] + b1.x, 0.f), fmaxf(acc[5] + b1.y, 0.f));
    h[3] = __floats2half2_rn(fmaxf(acc[6] + b1.z, 0.f), fmaxf(acc[7] + b1.w, 0.f));
    ((uint4*)(g_bufH + (size_t)w * 256))[lane] = *(uint4*)h;
}

// ---------------- agg layer 2 (unweighted sum of prescaled rows) + head ------
__global__ __launch_bounds__(256) void k_agg_final(const float* __restrict__ b2,
                                                   const float* __restrict__ Wl,
                                                   const float* __restrict__ bl,
                                                   float* __restrict__ out) {
    int w = (blockIdx.x * blockDim.x + threadIdx.x) >> 5;
    int lane = threadIdx.x & 31;
    if (w >= N_NODES) return;
    int beg = g_offs[w], end = g_offs[w + 1];
    float disw = g_dis[w];
    float acc[8];
#pragma unroll
    for (int j = 0; j < 8; j++) acc[j] = 0.f;
    agg_edges_add(acc, g_bufT2, beg, end, lane);
#pragma unroll
    for (int j = 0; j < 8; j++) acc[j] *= disw;

    float4 b0 = ((const float4*)b2)[lane * 2];
    float4 b1 = ((const float4*)b2)[lane * 2 + 1];
    float4 w0 = ((const float4*)Wl)[lane * 2];
    float4 w1 = ((const float4*)Wl)[lane * 2 + 1];
    float s =
        fmaxf(acc[0] + b0.x, 0.f) * w0.x + fmaxf(acc[1] + b0.y, 0.f) * w0.y +
        fmaxf(acc[2] + b0.z, 0.f) * w0.z + fmaxf(acc[3] + b0.w, 0.f) * w0.w +
        fmaxf(acc[4] + b1.x, 0.f) * w1.x + fmaxf(acc[5] + b1.y, 0.f) * w1.y +
        fmaxf(acc[6] + b1.z, 0.f) * w1.z + fmaxf(acc[7] + b1.w, 0.f) * w1.w;
#pragma unroll
    for (int o = 16; o > 0; o >>= 1) s += __shfl_xor_sync(0xFFFFFFFFu, s, o);
    if (lane == 0) out[w] = s + bl[0];
}

// ---------------- launch ----------------
extern "C" void kernel_launch(void* const* d_in, const int* in_sizes, int n_in,
                              void* d_out, int out_size) {
    const float* x  = (const float*)d_in[0];
    const int*   ei = (const int*)d_in[1];     // edge_index is int32 (JAX x64 disabled)
    const float* W1 = (const float*)d_in[2];
    const float* b1 = (const float*)d_in[3];
    const float* W2 = (const float*)d_in[4];
    const float* b2 = (const float*)d_in[5];
    const float* Wl = (const float*)d_in[6];
    const float* bl = (const float*)d_in[7];
    float* out = (float*)d_out;

    // one-time host-side setup (no device allocations)
    static bool inited = false;
    static cudaStream_t sB;
    static cudaEvent_t evF1, evJ1, evF2, evJ2;
    static __half *pT, *pT2, *pH;
    static int* pDeg;
    if (!inited) {
        cudaStreamCreate(&sB);
        cudaEventCreateWithFlags(&evF1, cudaEventDisableTiming);
        cudaEventCreateWithFlags(&evJ1, cudaEventDisableTiming);
        cudaEventCreateWithFlags(&evF2, cudaEventDisableTiming);
        cudaEventCreateWithFlags(&evJ2, cudaEventDisableTiming);
        void* p;
        cudaGetSymbolAddress(&p, g_bufT);  pT  = (__half*)p;
        cudaGetSymbolAddress(&p, g_bufT2); pT2 = (__half*)p;
        cudaGetSymbolAddress(&p, g_bufH);  pH  = (__half*)p;
        cudaGetSymbolAddress(&p, g_deg);   pDeg = (int*)p;
        inited = true;
    }

    int E = in_sizes[1] / 2;
    int nblk = (N_NODES + SCAN_B - 1) / SCAN_B;           // 98
    int node_blocks = (N_NODES + 255) / 256;              // 391
    int agg_blocks = (N_NODES * 32 + 255) / 256;          // 12500
    int agg1a_blocks = (HALF_ROWS * 32 + 255) / 256;              // 6256
    int agg1b_blocks = ((N_NODES - HALF_ROWS) * 32 + 255) / 256;  // 6244

    // zero degree counts (self-loop "+1" folded into scans)
    cudaMemsetAsync(pDeg, 0, N_NODES * sizeof(int), 0);

    // GEMM1 first half (rows [0, 50048)) overlapped with degree histogram
    k_gemm_aux<float, 1><<<AUX_BLOCKS + HALF_TILES * 2, 256>>>(
        x, W1, pT, N_NODES, 0, HALF_TILES, ei, E, AUX_BLOCKS, 0);

    // fork: GEMM1 second half (pure tensor work, independent of scans/fill)
    cudaEventRecord(evF1, 0);
    cudaStreamWaitEvent(sB, evF1, 0);
    k_gemm_aux<float, 0><<<HALF_TILES * 2, 256, 0, sB>>>(
        x, W1, pT, N_NODES, HALF_TILES, HALF_TILES, nullptr, 0, 0, 0);
    cudaEventRecord(evJ1, sB);

    // concurrently on capture stream: scans + wide-grid CSR fill
    k_scan1<<<nblk, SCAN_B>>>();
    k_scan2<<<1, SCAN_B>>>(nblk);
    k_scan3<<<node_blocks, 256>>>();
    k_fill<<<2048, 256>>>(ei, E);

    // join: agg1 needs ALL of bufT + complete CSR
    cudaStreamWaitEvent((cudaStream_t)0, evJ1, 0);

    // agg1 first half
    k_agg_relu<<<agg1a_blocks, 256>>>(b1, 0, HALF_ROWS);

    // fork: GEMM2 rows [0, 50048) (reads bufH[0,50048), writes bufT2, prescaled)
    //       concurrent with agg1 second half
    cudaEventRecord(evF2, 0);
    cudaStreamWaitEvent(sB, evF2, 0);
    k_gemm_aux<__half, 0><<<HALF_TILES * 2, 256, 0, sB>>>(
        pH, W2, pT2, N_NODES, 0, HALF_TILES, nullptr, 0, 0, 1);
    cudaEventRecord(evJ2, sB);

    k_agg_relu<<<agg1b_blocks, 256>>>(b1, HALF_ROWS, N_NODES);

    // join, then GEMM2 second half
    cudaStreamWaitEvent((cudaStream_t)0, evJ2, 0);
    k_gemm_aux<__half, 0><<<HALF_TILES * 2, 256>>>(
        pH, W2, pT2, N_NODES, HALF_TILES, HALF_TILES, nullptr, 0, 0, 1);

    // layer-2 aggregation (unweighted; weights folded into bufT2) + head
    k_agg_final<<<agg_blocks, 256>>>(b2, Wl, bl, out);
}